// round 16
// baseline (speedup 1.0000x reference)
#include <cuda_runtime.h>
#include <cuda_bf16.h>
#include <cstdint>

// Problem constants (VOCAB=32000, D_MODEL=512, BATCH=8, SEQ=4096)
constexpr int B_ = 8;
constexpr int S_ = 4096;
constexpr int D_ = 512;
constexpr int NBLK = 1024;              // single-wave grid; 2 units per block

// pe[s,d] = sin(angle) for even d, cos(angle) for odd d,
// angle = s / 10000^(2d/512)  (per-index exponent, faithful to reference)
__device__ __forceinline__ float pe_val(float sf, int d) {
    const float C       = -0.05190512648261504f;  // -2/512 * log2(10000)
    const float INV2PI  =  0.15915494309189535f;
    const float PI2_HI  =  6.2831855f;            // fl32(2*pi)
    const float PI2_LO  = -1.7484556e-7f;         // 2*pi - PI2_HI
    const float PIO2    =  1.5707963267948966f;

    float w   = exp2f((float)d * C);              // 10000^(-2d/512)
    float off = (d & 1) ? PIO2 : 0.0f;            // odd d -> cos = sin(x + pi/2)
    float ang = fmaf(sf, w, off);
    float k   = rintf(ang * INV2PI);
    float r   = fmaf(k, -PI2_HI, ang);
    r         = fmaf(k, -PI2_LO, r);
    return __sinf(r);                             // |r| <= pi -> accurate
}

__device__ __forceinline__ float4 pe4_of(int s, int t) {
    const float sf = (float)s;
    const int d0 = t * 4;
    float4 p;
    p.x = pe_val(sf, d0 + 0);
    p.y = pe_val(sf, d0 + 1);
    p.z = pe_val(sf, d0 + 2);
    p.w = pe_val(sf, d0 + 3);
    return p;
}

__global__ __launch_bounds__(256) void emb_pe_kernel(
    const int*   __restrict__ tokens,   // [B, S]
    const float* __restrict__ table,    // [V, D]
    float*       __restrict__ out)      // [B, S, D]
{
    // Unit u covers s-pair (2u, 2u+1); threads 0..127 -> even s, 128..255 -> odd.
    const int half = threadIdx.x >> 7;
    const int t    = threadIdx.x & 127;

    const int s0 = blockIdx.x * 2 + half;              // unit 0
    const int s1 = (blockIdx.x + NBLK) * 2 + half;     // unit 1

    const float4* __restrict__ tab4 = reinterpret_cast<const float4*>(table);
    float4* __restrict__ out4 = reinterpret_cast<float4*>(out);

    // Tokens for both units up front (uniform -> warp broadcast).
    int tokA[B_], tokB[B_];
    #pragma unroll
    for (int b = 0; b < B_; b++) tokA[b] = __ldg(tokens + b * S_ + s0);
    #pragma unroll
    for (int b = 0; b < B_; b++) tokB[b] = __ldg(tokens + b * S_ + s1);

    // Unit 0 gathers (MLP = 8).
    float4 vA[B_];
    #pragma unroll
    for (int b = 0; b < B_; b++)
        vA[b] = __ldg(tab4 + (size_t)tokA[b] * (D_ / 4) + t);

    // Trig for unit 0 overlaps unit 0's in-flight gathers.
    float4 peA = pe4_of(s0, t);

    // Software pipeline: issue unit 1's gathers BEFORE unit 0's stores, so
    // their latency hides under store issue + unit-1 trig.
    float4 vB[B_];
    #pragma unroll
    for (int b = 0; b < B_; b++)
        vB[b] = __ldg(tab4 + (size_t)tokB[b] * (D_ / 4) + t);

    // Unit 0: add + streaming store.
    #pragma unroll
    for (int b = 0; b < B_; b++) {
        float4 r = vA[b];
        r.x += peA.x; r.y += peA.y; r.z += peA.z; r.w += peA.w;
        __stcs(out4 + ((size_t)b * S_ + s0) * (D_ / 4) + t, r);
    }

    // Trig for unit 1 overlaps its remaining gather latency.
    float4 peB = pe4_of(s1, t);

    // Unit 1: add + streaming store.
    #pragma unroll
    for (int b = 0; b < B_; b++) {
        float4 r = vB[b];
        r.x += peB.x; r.y += peB.y; r.z += peB.z; r.w += peB.w;
        __stcs(out4 + ((size_t)b * S_ + s1) * (D_ / 4) + t, r);
    }
}

extern "C" void kernel_launch(void* const* d_in, const int* in_sizes, int n_in,
                              void* d_out, int out_size) {
    const int*   tokens = (const int*)d_in[0];     // [8, 4096] int32
    const float* table  = (const float*)d_in[1];   // [32000, 512] float32
    float*       out    = (float*)d_out;           // [8, 4096, 512] float32
    (void)in_sizes; (void)n_in; (void)out_size;

    emb_pe_kernel<<<NBLK, 256>>>(tokens, table, out);
}